// round 14
// baseline (speedup 1.0000x reference)
#include <cuda_runtime.h>
#include <cstdint>
#include <cstddef>

#define BM 128
#define BN 128
#define BK 32
#define SKW 36                         // smem row stride in words (128B data + 16B skew)
#define STAGES 3
#define MAT_WORDS (BM * SKW)           // 4608 words per matrix per stage
#define STAGE_WORDS (2 * MAT_WORDS)    // A + B = 9216 words
#define GEMM_SMEM (STAGES * STAGE_WORDS * 4)   // 110592 B -> 2 CTAs/SM

// ---------------- scratch (allocation-free rule: __device__ globals) ----------------
static __device__ float g_qkv [(size_t)16384 * 3072];   // 201 MB
static __device__ float g_attn[(size_t)16384 * 1024];   //  67 MB
static __device__ float g_xr  [(size_t)16384 * 1024];   //  64 MB  (tf32-rounded x)
static __device__ float g_wqkv[(size_t)3072  * 1024];   //  12 MB  (tf32-rounded Wqkv)
static __device__ float g_wo  [(size_t)1024  * 1024];   //   4 MB  (tf32-rounded Wo)

__device__ __forceinline__ unsigned f2tf(float f) {
    unsigned u;
    asm("cvt.rna.tf32.f32 %0, %1;" : "=r"(u) : "f"(f));
    return u;
}

__device__ __forceinline__ uint32_t smem_u32(const void* p) {
    uint32_t a;
    asm("{ .reg .u64 t; cvta.to.shared.u64 t, %1; cvt.u32.u64 %0, t; }"
        : "=r"(a) : "l"(p));
    return a;
}

__device__ __forceinline__ void mma_tf32(float c[4], const unsigned a[4], const unsigned b[2]) {
    asm volatile(
        "mma.sync.aligned.m16n8k8.row.col.f32.tf32.tf32.f32 "
        "{%0,%1,%2,%3}, {%4,%5,%6,%7}, {%8,%9}, {%0,%1,%2,%3};\n"
        : "+f"(c[0]), "+f"(c[1]), "+f"(c[2]), "+f"(c[3])
        : "r"(a[0]), "r"(a[1]), "r"(a[2]), "r"(a[3]), "r"(b[0]), "r"(b[1]));
}

// ---------------- tf32 pre-rounding pass ----------------
__global__ void __launch_bounds__(256)
round_tf32(const float* __restrict__ in, float* __restrict__ out, int n4)
{
    int i = blockIdx.x * blockDim.x + threadIdx.x;
    const int stride = gridDim.x * blockDim.x;
    const float4* src = (const float4*)in;
    float4* dst = (float4*)out;
    for (; i < n4; i += stride) {
        float4 v = src[i];
        v.x = __uint_as_float(f2tf(v.x));
        v.y = __uint_as_float(f2tf(v.y));
        v.z = __uint_as_float(f2tf(v.z));
        v.w = __uint_as_float(f2tf(v.w));
        dst[i] = v;
    }
}

// ---------------- tf32 NT-GEMM: 256 thr, 8 warps 64x32, BK=32, 3-stage cp.async ----------------
// C[m,n] = sum_k A[m,k]*B[n,k] (+bias[n]); A,B already tf32-rounded fp32, row-major, K contiguous.
template <bool HAS_BIAS>
__global__ void __launch_bounds__(256, 2)
gemm_tf32_cp(const float* __restrict__ A, const float* __restrict__ Bm,
             const float* __restrict__ bias, float* __restrict__ C,
             int M, int Nd, int K)
{
    extern __shared__ __align__(16) unsigned sm[];
    const uint32_t sbase = smem_u32(sm);

    const int tid  = threadIdx.x;
    const int warp = tid >> 5;
    const int lane = tid & 31;
    const int g    = lane >> 2;   // 0..7
    const int c    = lane & 3;    // 0..3

    const int bm0 = blockIdx.y * BM;
    const int bn0 = blockIdx.x * BN;

    const int wm = (warp >> 2) * 64;   // 2x4 warp raster, 64x32 warp tile
    const int wn = (warp &  3) * 32;

    // producer mapping: q = 16B quad within 128B row, rows r0+32i (i=0..3) per matrix
    const int q  = tid & 7;       // 0..7
    const int r0 = tid >> 3;      // 0..31
    const float* Ag = A  + (size_t)(bm0 + r0) * K + q * 4;
    const float* Bg = Bm + (size_t)(bn0 + r0) * K + q * 4;

    float acc[4][4][4];
    #pragma unroll
    for (int i = 0; i < 4; i++)
        #pragma unroll
        for (int j = 0; j < 4; j++)
            #pragma unroll
            for (int r = 0; r < 4; r++) acc[i][j][r] = 0.f;

    const int nChunks = K / BK;   // 32

    // per-thread smem byte dst (stage 0): 4 rows per matrix
    uint32_t dA[4];
    #pragma unroll
    for (int i = 0; i < 4; i++)
        dA[i] = sbase + (uint32_t)(((r0 + 32 * i) * SKW + q * 4) * 4);

    // ---- prologue: stages 0..STAGES-2 ----
    #pragma unroll
    for (int s = 0; s < STAGES - 1; s++) {
        const uint32_t so = (uint32_t)(s * STAGE_WORDS * 4);
        #pragma unroll
        for (int i = 0; i < 4; i++) {
            const float* ga = Ag + (size_t)(32 * i) * K + s * BK;
            const float* gb = Bg + (size_t)(32 * i) * K + s * BK;
            asm volatile("cp.async.cg.shared.global [%0], [%1], 16;" :: "r"(dA[i] + so), "l"(ga));
            asm volatile("cp.async.cg.shared.global [%0], [%1], 16;" :: "r"(dA[i] + so + MAT_WORDS * 4), "l"(gb));
        }
        asm volatile("cp.async.commit_group;");
    }

    for (int it = 0; it < nChunks; ++it) {
        asm volatile("cp.async.wait_group %0;" :: "n"(STAGES - 2));
        __syncthreads();

        // issue stage for chunk it+STAGES-1 (stage consumed at iter it-1; barrier above protects it)
        const int kc = it + STAGES - 1;
        if (kc < nChunks) {
            const uint32_t so = (uint32_t)((kc % STAGES) * STAGE_WORDS * 4);
            #pragma unroll
            for (int i = 0; i < 4; i++) {
                const float* ga = Ag + (size_t)(32 * i) * K + kc * BK;
                const float* gb = Bg + (size_t)(32 * i) * K + kc * BK;
                asm volatile("cp.async.cg.shared.global [%0], [%1], 16;" :: "r"(dA[i] + so), "l"(ga));
                asm volatile("cp.async.cg.shared.global [%0], [%1], 16;" :: "r"(dA[i] + so + MAT_WORDS * 4), "l"(gb));
            }
        }
        asm volatile("cp.async.commit_group;");

        // compute on stage it%STAGES : 4 k8-steps
        const unsigned* __restrict__ Acur = sm + (it % STAGES) * STAGE_WORDS;
        const unsigned* __restrict__ Bcur = Acur + MAT_WORDS;

        #pragma unroll
        for (int ks = 0; ks < 4; ks++) {
            const int kk = ks * 8;
            unsigned af[4][4];
            #pragma unroll
            for (int i = 0; i < 4; i++) {
                const int base = (wm + i * 16 + g) * SKW + kk + c;
                af[i][0] = Acur[base];
                af[i][1] = Acur[base + 8 * SKW];
                af[i][2] = Acur[base + 4];
                af[i][3] = Acur[base + 8 * SKW + 4];
            }
            unsigned bf[4][2];
            #pragma unroll
            for (int j = 0; j < 4; j++) {
                const int base = (wn + j * 8 + g) * SKW + kk + c;
                bf[j][0] = Bcur[base];
                bf[j][1] = Bcur[base + 4];
            }
            #pragma unroll
            for (int i = 0; i < 4; i++)
                #pragma unroll
                for (int j = 0; j < 4; j++)
                    mma_tf32(acc[i][j], af[i], bf[j]);
        }
    }

    // ---- epilogue ----
    #pragma unroll
    for (int i = 0; i < 4; i++) {
        const int row = bm0 + wm + i * 16 + g;
        #pragma unroll
        for (int j = 0; j < 4; j++) {
            const int col = bn0 + wn + j * 8 + c * 2;
            float2 add = make_float2(0.f, 0.f);
            if (HAS_BIAS) add = *(const float2*)(bias + col);
            float2 v0 = make_float2(acc[i][j][0] + add.x, acc[i][j][1] + add.y);
            float2 v1 = make_float2(acc[i][j][2] + add.x, acc[i][j][3] + add.y);
            *(float2*)(C + (size_t)row       * Nd + col) = v0;
            *(float2*)(C + (size_t)(row + 8) * Nd + col) = v1;
        }
    }
}

// ---------------- per-position cross-head attention ----------------
__global__ void __launch_bounds__(128)
attn_kernel(const float* __restrict__ qkv, float* __restrict__ attn)
{
    __shared__ float s[3072];
    __shared__ float sS[16 * 17];
    __shared__ float sW[16 * 17];

    const int tid = threadIdx.x;
    const size_t m = blockIdx.x;

    const float4* src = (const float4*)(qkv + m * 3072);
    float4* dst = (float4*)s;
    #pragma unroll
    for (int i = 0; i < 6; i++) dst[tid + i * 128] = src[tid + i * 128];
    __syncthreads();

    const float* q = s;
    const float* k = s + 1024;
    const float* v = s + 2048;

    #pragma unroll
    for (int e = 0; e < 2; e++) {
        const int idx = tid + e * 128;
        const int h  = idx >> 4;
        const int gg = idx & 15;
        float sum = 0.f;
        #pragma unroll
        for (int d = 0; d < 64; d++) {
            const int dd = (d + gg) & 63;   // rotation kills stride-64 bank conflicts
            sum += q[h * 64 + dd] * k[gg * 64 + dd];
        }
        sS[h * 17 + gg] = sum * 0.03125f;   // 1/sqrt(1024)
    }
    __syncthreads();

    if (tid < 16) {
        float mx = -1e30f;
        #pragma unroll
        for (int j = 0; j < 16; j++) mx = fmaxf(mx, sS[tid * 17 + j]);
        float w[16], sum = 0.f;
        #pragma unroll
        for (int j = 0; j < 16; j++) { w[j] = __expf(sS[tid * 17 + j] - mx); sum += w[j]; }
        const float inv = 1.f / sum;
        #pragma unroll
        for (int j = 0; j < 16; j++) sW[tid * 17 + j] = w[j] * inv;
    }
    __syncthreads();

    const int h  = tid >> 3;
    const int d0 = (tid & 7) * 8;
    float out[8];
    #pragma unroll
    for (int j = 0; j < 8; j++) out[j] = 0.f;
    #pragma unroll
    for (int gg = 0; gg < 16; gg++) {
        const float w = sW[h * 17 + gg];
        #pragma unroll
        for (int j = 0; j < 8; j++) out[j] += w * v[gg * 64 + d0 + j];
    }
    float4* o4 = (float4*)(attn + m * 1024 + h * 64 + d0);
    o4[0] = make_float4(__uint_as_float(f2tf(out[0])), __uint_as_float(f2tf(out[1])),
                        __uint_as_float(f2tf(out[2])), __uint_as_float(f2tf(out[3])));
    o4[1] = make_float4(__uint_as_float(f2tf(out[4])), __uint_as_float(f2tf(out[5])),
                        __uint_as_float(f2tf(out[6])), __uint_as_float(f2tf(out[7])));
}

// ---------------- launch ----------------
extern "C" void kernel_launch(void* const* d_in, const int* in_sizes, int n_in,
                              void* d_out, int out_size)
{
    const float* x    = (const float*)d_in[0];   // (4,4096,1024)
    const float* Wqkv = (const float*)d_in[1];   // (3072,1024)
    const float* Wo   = (const float*)d_in[2];   // (1024,1024)
    const float* bo   = (const float*)d_in[3];   // (1024)
    float* out = (float*)d_out;

    float *qkv = nullptr, *attn = nullptr, *xr = nullptr, *wqkvr = nullptr, *wor = nullptr;
    cudaGetSymbolAddress((void**)&qkv,   g_qkv);
    cudaGetSymbolAddress((void**)&attn,  g_attn);
    cudaGetSymbolAddress((void**)&xr,    g_xr);
    cudaGetSymbolAddress((void**)&wqkvr, g_wqkv);
    cudaGetSymbolAddress((void**)&wor,   g_wo);

    cudaFuncSetAttribute(gemm_tf32_cp<false>, cudaFuncAttributeMaxDynamicSharedMemorySize, GEMM_SMEM);
    cudaFuncSetAttribute(gemm_tf32_cp<true >, cudaFuncAttributeMaxDynamicSharedMemorySize, GEMM_SMEM);

    const int M = 16384, K = 1024;

    // tf32 pre-rounding (cheap, HBM-streaming)
    round_tf32<<<4096, 256>>>(x,    xr,    (16384 * 1024) / 4);
    round_tf32<<<1536, 256>>>(Wqkv, wqkvr, (3072  * 1024) / 4);
    round_tf32<<<512,  256>>>(Wo,   wor,   (1024  * 1024) / 4);

    gemm_tf32_cp<false><<<dim3(3072 / BN, M / BM), 256, GEMM_SMEM>>>(xr,   wqkvr, nullptr, qkv, M, 3072, K);
    attn_kernel<<<M, 128>>>(qkv, attn);
    gemm_tf32_cp<true ><<<dim3(1024 / BN, M / BM), 256, GEMM_SMEM>>>(attn, wor,   bo,      out, M, 1024, K);
}